// round 1
// baseline (speedup 1.0000x reference)
#include <cuda_runtime.h>
#include <cuda_bf16.h>

// Problem constants
#define BB   4
#define TT   4096
#define EE   1024
#define HD   64
#define MROWS (BB * TT)          // 16384
#define SCALE 0.03125f           // E^-0.5 = 1/32  (reference scales by embed_size**-0.5)

// Scratch for projected q,k,v  ([B*T, 64] each, fp32) — static device arrays (no alloc)
__device__ float g_q[MROWS * HD];
__device__ float g_k[MROWS * HD];
__device__ float g_v[MROWS * HD];

// ---------------------------------------------------------------------------
// Kernel 1: QKV projection.  C[m,h] = sum_e A[m,e] * W[h,e]
// Grid: (MROWS/64, 3). Block: 256 threads. BM=64, BN=64, BK=16, 4x4 microtile.
// ---------------------------------------------------------------------------
__global__ __launch_bounds__(256) void qkv_kernel(
    const float* __restrict__ emb,
    const float* __restrict__ Wq,
    const float* __restrict__ Wk,
    const float* __restrict__ Wv)
{
    const float* W   = (blockIdx.y == 0) ? Wq : (blockIdx.y == 1) ? Wk : Wv;
    float*       out = (blockIdx.y == 0) ? g_q : (blockIdx.y == 1) ? g_k : g_v;

    __shared__ float As[64][17];   // [row][kk], padded
    __shared__ float Ws[16][64];   // [kk][col]

    const int t  = threadIdx.x;
    const int tx = t & 15;         // 0..15 -> output col group
    const int ty = t >> 4;         // 0..15 -> output row group
    const int m0 = blockIdx.x * 64;

    float acc[4][4];
#pragma unroll
    for (int i = 0; i < 4; i++)
#pragma unroll
        for (int j = 0; j < 4; j++) acc[i][j] = 0.0f;

    for (int k0 = 0; k0 < EE; k0 += 16) {
        // load A tile (64 x 16): one float4 per thread, coalesced
        {
            int row = t >> 2;
            int kk  = (t & 3) * 4;
            float4 v = *(const float4*)&emb[(size_t)(m0 + row) * EE + k0 + kk];
            As[row][kk + 0] = v.x; As[row][kk + 1] = v.y;
            As[row][kk + 2] = v.z; As[row][kk + 3] = v.w;
        }
        // load W tile (16 x 64), transposed into Ws[kk][col]
        {
            int col = t & 63;
            int kkb = (t >> 6) * 4;
            float4 v = *(const float4*)&W[(size_t)col * EE + k0 + kkb];
            Ws[kkb + 0][col] = v.x; Ws[kkb + 1][col] = v.y;
            Ws[kkb + 2][col] = v.z; Ws[kkb + 3][col] = v.w;
        }
        __syncthreads();

#pragma unroll
        for (int kk = 0; kk < 16; kk++) {
            float a0 = As[ty * 4 + 0][kk];
            float a1 = As[ty * 4 + 1][kk];
            float a2 = As[ty * 4 + 2][kk];
            float a3 = As[ty * 4 + 3][kk];
            float4 b = *(const float4*)&Ws[kk][tx * 4];
            acc[0][0] += a0 * b.x; acc[0][1] += a0 * b.y; acc[0][2] += a0 * b.z; acc[0][3] += a0 * b.w;
            acc[1][0] += a1 * b.x; acc[1][1] += a1 * b.y; acc[1][2] += a1 * b.z; acc[1][3] += a1 * b.w;
            acc[2][0] += a2 * b.x; acc[2][1] += a2 * b.y; acc[2][2] += a2 * b.z; acc[2][3] += a2 * b.w;
            acc[3][0] += a3 * b.x; acc[3][1] += a3 * b.y; acc[3][2] += a3 * b.z; acc[3][3] += a3 * b.w;
        }
        __syncthreads();
    }

#pragma unroll
    for (int i = 0; i < 4; i++) {
        float4 v = make_float4(acc[i][0], acc[i][1], acc[i][2], acc[i][3]);
        *(float4*)&out[(size_t)(m0 + ty * 4 + i) * HD + tx * 4] = v;
    }
}

// ---------------------------------------------------------------------------
// Kernel 2: flash attention (causal), 64x64 tiles.
// Grid: (T/64, B). Block: 256 threads (16x16 microtile grid, 4x4 per thread).
// Dynamic SMEM layout (floats), all row strides = 68 (16B-aligned, bank-skewed):
//   QsT[64][68]  : Q transposed [h][q]
//   KsT[64][68]  : K transposed [h][k]
//   Vs [64][68]  : V natural    [k][h]
//   Ss [64][68]  : scores / probs [q][k]
//   m[64], l[64], rf[64]
// ---------------------------------------------------------------------------
#define TILE   64
#define LDP    68
#define SM_QT  0
#define SM_KT  (SM_QT + TILE * LDP)
#define SM_V   (SM_KT + TILE * LDP)
#define SM_S   (SM_V  + TILE * LDP)
#define SM_M   (SM_S  + TILE * LDP)
#define SM_L   (SM_M  + TILE)
#define SM_RF  (SM_L  + TILE)
#define SMEM_FLOATS (SM_RF + TILE)

__global__ __launch_bounds__(256) void attn_kernel(float* __restrict__ out)
{
    extern __shared__ float sm[];
    float* QsT = sm + SM_QT;
    float* KsT = sm + SM_KT;
    float* Vs  = sm + SM_V;
    float* Ss  = sm + SM_S;
    float* smM = sm + SM_M;
    float* smL = sm + SM_L;
    float* smR = sm + SM_RF;

    const int t  = threadIdx.x;
    const int tx = t & 15;
    const int ty = t >> 4;
    const int qt = blockIdx.x;           // q tile index
    const int b  = blockIdx.y;
    const int q0 = qt * TILE;
    const size_t baseRow = (size_t)b * TT;

    // init softmax state
    if (t < TILE) { smM[t] = -1e30f; smL[t] = 0.0f; }

    // load Q tile transposed: QsT[h][q]
    for (int i4 = t; i4 < TILE * (HD / 4); i4 += 256) {
        int h4 = (i4 & 15) * 4;
        int q  = i4 >> 4;
        float4 v = *(const float4*)&g_q[(baseRow + q0 + q) * HD + h4];
        QsT[(h4 + 0) * LDP + q] = v.x;
        QsT[(h4 + 1) * LDP + q] = v.y;
        QsT[(h4 + 2) * LDP + q] = v.z;
        QsT[(h4 + 3) * LDP + q] = v.w;
    }
    __syncthreads();

    float o[4][4];
#pragma unroll
    for (int i = 0; i < 4; i++)
#pragma unroll
        for (int j = 0; j < 4; j++) o[i][j] = 0.0f;

    const int qr = ty * 4;
    const int cc = tx * 4;   // column group (k for scores, h for output)

    for (int kt = 0; kt <= qt; kt++) {
        const int k0 = kt * TILE;

        // load K tile transposed + V tile natural
        for (int i4 = t; i4 < TILE * (HD / 4); i4 += 256) {
            int h4 = (i4 & 15) * 4;
            int k  = i4 >> 4;
            float4 kv = *(const float4*)&g_k[(baseRow + k0 + k) * HD + h4];
            KsT[(h4 + 0) * LDP + k] = kv.x;
            KsT[(h4 + 1) * LDP + k] = kv.y;
            KsT[(h4 + 2) * LDP + k] = kv.z;
            KsT[(h4 + 3) * LDP + k] = kv.w;
            float4 vv = *(const float4*)&g_v[(baseRow + k0 + k) * HD + h4];
            *(float4*)&Vs[k * LDP + h4] = vv;
        }
        __syncthreads();

        // S = Q K^T * scale   (4x4 microtile per thread)
        float s[4][4];
#pragma unroll
        for (int i = 0; i < 4; i++)
#pragma unroll
            for (int j = 0; j < 4; j++) s[i][j] = 0.0f;

#pragma unroll 4
        for (int h = 0; h < HD; h++) {
            float4 a = *(const float4*)&QsT[h * LDP + qr];
            float4 bk = *(const float4*)&KsT[h * LDP + cc];
            s[0][0] += a.x * bk.x; s[0][1] += a.x * bk.y; s[0][2] += a.x * bk.z; s[0][3] += a.x * bk.w;
            s[1][0] += a.y * bk.x; s[1][1] += a.y * bk.y; s[1][2] += a.y * bk.z; s[1][3] += a.y * bk.w;
            s[2][0] += a.z * bk.x; s[2][1] += a.z * bk.y; s[2][2] += a.z * bk.z; s[2][3] += a.z * bk.w;
            s[3][0] += a.w * bk.x; s[3][1] += a.w * bk.y; s[3][2] += a.w * bk.z; s[3][3] += a.w * bk.w;
        }

        // scale + causal mask (only on diagonal tile) + store to Ss
        const bool diag = (kt == qt);
#pragma unroll
        for (int i = 0; i < 4; i++)
#pragma unroll
            for (int j = 0; j < 4; j++) {
                float v = s[i][j] * SCALE;
                if (diag && (cc + j) > (qr + i)) v = -1e30f;
                Ss[(qr + i) * LDP + (cc + j)] = v;
            }
        __syncthreads();

        // online softmax: 4 lanes per row (r = t/4, part = t%3..)
        {
            const int r    = t >> 2;
            const int part = t & 3;
            const int cb   = part * 16;
            float mx = -1e30f;
#pragma unroll
            for (int c = 0; c < 16; c++) mx = fmaxf(mx, Ss[r * LDP + cb + c]);
            mx = fmaxf(mx, __shfl_xor_sync(0xffffffffu, mx, 1));
            mx = fmaxf(mx, __shfl_xor_sync(0xffffffffu, mx, 2));
            const float m_old = smM[r];
            const float m_new = fmaxf(m_old, mx);
            float sum = 0.0f;
#pragma unroll
            for (int c = 0; c < 16; c++) {
                float p = __expf(Ss[r * LDP + cb + c] - m_new);
                Ss[r * LDP + cb + c] = p;
                sum += p;
            }
            sum += __shfl_xor_sync(0xffffffffu, sum, 1);
            sum += __shfl_xor_sync(0xffffffffu, sum, 2);
            if (part == 0) {
                const float rf = __expf(m_old - m_new);
                smR[r] = rf;
                smM[r] = m_new;
                smL[r] = smL[r] * rf + sum;
            }
        }
        __syncthreads();

        // rescale O, then O += P * V
        float f0 = smR[qr + 0], f1 = smR[qr + 1], f2 = smR[qr + 2], f3 = smR[qr + 3];
#pragma unroll
        for (int j = 0; j < 4; j++) {
            o[0][j] *= f0; o[1][j] *= f1; o[2][j] *= f2; o[3][j] *= f3;
        }
#pragma unroll 4
        for (int k = 0; k < TILE; k++) {
            float a0 = Ss[(qr + 0) * LDP + k];
            float a1 = Ss[(qr + 1) * LDP + k];
            float a2 = Ss[(qr + 2) * LDP + k];
            float a3 = Ss[(qr + 3) * LDP + k];
            float4 bv = *(const float4*)&Vs[k * LDP + cc];
            o[0][0] += a0 * bv.x; o[0][1] += a0 * bv.y; o[0][2] += a0 * bv.z; o[0][3] += a0 * bv.w;
            o[1][0] += a1 * bv.x; o[1][1] += a1 * bv.y; o[1][2] += a1 * bv.z; o[1][3] += a1 * bv.w;
            o[2][0] += a2 * bv.x; o[2][1] += a2 * bv.y; o[2][2] += a2 * bv.z; o[2][3] += a2 * bv.w;
            o[3][0] += a3 * bv.x; o[3][1] += a3 * bv.y; o[3][2] += a3 * bv.z; o[3][3] += a3 * bv.w;
        }
        __syncthreads();   // protect Ks/Vs/Ss before next iteration overwrites
    }

    // final normalize + write out[b, q0+qr+i, cc+j]
#pragma unroll
    for (int i = 0; i < 4; i++) {
        const float inv = 1.0f / smL[qr + i];
        float4 v = make_float4(o[i][0] * inv, o[i][1] * inv, o[i][2] * inv, o[i][3] * inv);
        *(float4*)&out[(baseRow + q0 + qr + i) * HD + cc] = v;
    }
}

// ---------------------------------------------------------------------------
extern "C" void kernel_launch(void* const* d_in, const int* in_sizes, int n_in,
                              void* d_out, int out_size)
{
    const float* emb = (const float*)d_in[0];
    const float* Wq  = (const float*)d_in[1];
    const float* Wk  = (const float*)d_in[2];
    const float* Wv  = (const float*)d_in[3];
    float* out = (float*)d_out;

    // QKV projection: grid (16384/64, 3)
    dim3 gq(MROWS / 64, 3);
    qkv_kernel<<<gq, 256>>>(emb, Wq, Wk, Wv);

    // Flash attention
    const int smem_bytes = SMEM_FLOATS * (int)sizeof(float);
    cudaFuncSetAttribute(attn_kernel, cudaFuncAttributeMaxDynamicSharedMemorySize, smem_bytes);
    dim3 ga(TT / TILE, BB);
    attn_kernel<<<ga, 256, smem_bytes>>>(out);
}

// round 2
// speedup vs baseline: 2.7582x; 2.7582x over previous
#include <cuda_runtime.h>
#include <cuda_bf16.h>

#define BB   4
#define TT   4096
#define EE   1024
#define HD   64
#define MROWS (BB * TT)
#define SCALE 0.03125f

// Scratch for projected q,k,v (tf32-rounded fp32)
__device__ float g_q[MROWS * HD];
__device__ float g_k[MROWS * HD];
__device__ float g_v[MROWS * HD];

__device__ __forceinline__ unsigned f2tf(float x) {
    unsigned r; asm("cvt.rna.tf32.f32 %0, %1;" : "=r"(r) : "f"(x)); return r;
}
__device__ __forceinline__ float f2tf_f(float x) { return __uint_as_float(f2tf(x)); }

__device__ __forceinline__ void mma_tf32(float c[4],
    unsigned a0, unsigned a1, unsigned a2, unsigned a3,
    unsigned b0, unsigned b1)
{
    asm volatile(
        "mma.sync.aligned.m16n8k8.row.col.f32.tf32.tf32.f32 "
        "{%0,%1,%2,%3}, {%4,%5,%6,%7}, {%8,%9}, {%0,%1,%2,%3};"
        : "+f"(c[0]), "+f"(c[1]), "+f"(c[2]), "+f"(c[3])
        : "r"(a0), "r"(a1), "r"(a2), "r"(a3), "r"(b0), "r"(b1));
}

// ---------------------------------------------------------------------------
// Kernel 1: QKV projection via tf32 MMA.  C[m,h] = sum_e A[m,e] * W[h,e]
// Grid: (MROWS/128, 3). Block 256 (8 warps). BM=128, BN=64, BK=16.
// Warp tile: 32 rows x 32 cols (2 m-subtiles x 4 n-subtiles of m16n8).
// ---------------------------------------------------------------------------
__global__ __launch_bounds__(256) void qkv_kernel(
    const float* __restrict__ emb,
    const float* __restrict__ Wq,
    const float* __restrict__ Wk,
    const float* __restrict__ Wv)
{
    const float* W   = (blockIdx.y == 0) ? Wq : (blockIdx.y == 1) ? Wk : Wv;
    float*       out = (blockIdx.y == 0) ? g_q : (blockIdx.y == 1) ? g_k : g_v;

    __shared__ float As[128][20];   // [m][k], tf32-rounded
    __shared__ float Ws[64][20];    // [n][k], tf32-rounded

    const int t    = threadIdx.x;
    const int warp = t >> 5;
    const int lane = t & 31;
    const int lr   = lane >> 2;   // 0..7
    const int lc   = lane & 3;    // 0..3
    const int wr   = warp >> 1;   // 0..3 (32-row groups)
    const int wc   = warp & 1;    // 0..1 (32-col groups)
    const int m0   = blockIdx.x * 128;

    float acc[2][4][4];
#pragma unroll
    for (int mm = 0; mm < 2; mm++)
#pragma unroll
        for (int nn = 0; nn < 4; nn++)
#pragma unroll
            for (int i = 0; i < 4; i++) acc[mm][nn][i] = 0.0f;

    for (int k0 = 0; k0 < EE; k0 += 16) {
        // A tile 128x16: 512 float4, 2 per thread
#pragma unroll
        for (int i = t; i < 512; i += 256) {
            int row = i >> 2, c4 = (i & 3) * 4;
            float4 v = *(const float4*)&emb[(size_t)(m0 + row) * EE + k0 + c4];
            As[row][c4 + 0] = f2tf_f(v.x); As[row][c4 + 1] = f2tf_f(v.y);
            As[row][c4 + 2] = f2tf_f(v.z); As[row][c4 + 3] = f2tf_f(v.w);
        }
        // W tile 64x16: 256 float4, 1 per thread
        {
            int row = t >> 2, c4 = (t & 3) * 4;
            float4 v = *(const float4*)&W[(size_t)row * EE + k0 + c4];
            Ws[row][c4 + 0] = f2tf_f(v.x); Ws[row][c4 + 1] = f2tf_f(v.y);
            Ws[row][c4 + 2] = f2tf_f(v.z); Ws[row][c4 + 3] = f2tf_f(v.w);
        }
        __syncthreads();

#pragma unroll
        for (int kk = 0; kk < 16; kk += 8) {
            unsigned a[2][4];
#pragma unroll
            for (int mm = 0; mm < 2; mm++) {
                int r = wr * 32 + mm * 16 + lr;
                a[mm][0] = __float_as_uint(As[r    ][kk + lc]);
                a[mm][1] = __float_as_uint(As[r + 8][kk + lc]);
                a[mm][2] = __float_as_uint(As[r    ][kk + 4 + lc]);
                a[mm][3] = __float_as_uint(As[r + 8][kk + 4 + lc]);
            }
#pragma unroll
            for (int nn = 0; nn < 4; nn++) {
                int n0 = wc * 32 + nn * 8;
                unsigned b0 = __float_as_uint(Ws[n0 + lr][kk + lc]);
                unsigned b1 = __float_as_uint(Ws[n0 + lr][kk + 4 + lc]);
                mma_tf32(acc[0][nn], a[0][0], a[0][1], a[0][2], a[0][3], b0, b1);
                mma_tf32(acc[1][nn], a[1][0], a[1][1], a[1][2], a[1][3], b0, b1);
            }
        }
        __syncthreads();
    }

    // write, rounded to tf32 so attention needs no further conversion
#pragma unroll
    for (int mm = 0; mm < 2; mm++)
#pragma unroll
        for (int nn = 0; nn < 4; nn++) {
            int r = m0 + wr * 32 + mm * 16 + lr;
            int c = wc * 32 + nn * 8 + 2 * lc;
            float2 v0 = make_float2(f2tf_f(acc[mm][nn][0]), f2tf_f(acc[mm][nn][1]));
            float2 v1 = make_float2(f2tf_f(acc[mm][nn][2]), f2tf_f(acc[mm][nn][3]));
            *(float2*)&out[(size_t)r * HD + c]       = v0;
            *(float2*)&out[(size_t)(r + 8) * HD + c] = v1;
        }
}

// ---------------------------------------------------------------------------
// Kernel 2: flash attention (causal), 64x64 tiles, tf32 MMA.
// Grid: (T/64, B). Block 256 (8 warps). Warp: 16 rows x 32 cols of the tile.
// ---------------------------------------------------------------------------
#define TILE  64
#define LDP   68   // Qs/Ks/Ss row stride (floats)
#define LDV   72   // Vs row stride (floats)
#define SM_Q  0
#define SM_K  (SM_Q + TILE * LDP)
#define SM_S  (SM_K + TILE * LDP)
#define SM_V  (SM_S + TILE * LDP)
#define SM_M  (SM_V + TILE * LDV)
#define SM_L  (SM_M + TILE)
#define SM_R  (SM_L + TILE)
#define SMEM_FLOATS (SM_R + TILE)

__global__ __launch_bounds__(256) void attn_kernel(float* __restrict__ out)
{
    extern __shared__ float sm[];
    float* Qs  = sm + SM_Q;   // [q][h]
    float* Ks  = sm + SM_K;   // [k][h]
    float* Ss  = sm + SM_S;   // [q][k]
    float* Vs  = sm + SM_V;   // [k][h]
    float* smM = sm + SM_M;
    float* smL = sm + SM_L;
    float* smR = sm + SM_R;

    const int t    = threadIdx.x;
    const int warp = t >> 5;
    const int lane = t & 31;
    const int lr   = lane >> 2;
    const int lc   = lane & 3;
    const int wr   = warp >> 1;   // 0..3: 16-row group
    const int wc   = warp & 1;    // 0..1: 32-col group
    const int qt   = blockIdx.x;
    const int b    = blockIdx.y;
    const int q0   = qt * TILE;
    const size_t baseRow = (size_t)b * TT;

    if (t < TILE) { smM[t] = -1e30f; smL[t] = 0.0f; }

    // load Q tile [q][h] (already tf32-rounded)
#pragma unroll
    for (int i = t; i < TILE * (HD / 4); i += 256) {
        int q = i >> 4, h4 = (i & 15) * 4;
        float4 v = *(const float4*)&g_q[(baseRow + q0 + q) * HD + h4];
        *(float4*)&Qs[q * LDP + h4] = v;
    }
    __syncthreads();

    float o[4][4];
#pragma unroll
    for (int nn = 0; nn < 4; nn++)
#pragma unroll
        for (int i = 0; i < 4; i++) o[nn][i] = 0.0f;

    for (int kt = 0; kt <= qt; kt++) {
        const int k0 = kt * TILE;

        // load K,V tiles
#pragma unroll
        for (int i = t; i < TILE * (HD / 4); i += 256) {
            int k = i >> 4, h4 = (i & 15) * 4;
            float4 kv = *(const float4*)&g_k[(baseRow + k0 + k) * HD + h4];
            *(float4*)&Ks[k * LDP + h4] = kv;
            float4 vv = *(const float4*)&g_v[(baseRow + k0 + k) * HD + h4];
            *(float4*)&Vs[k * LDV + h4] = vv;
        }
        __syncthreads();

        // S = Q K^T (tf32 MMA), warp computes 16x32
        float s[4][4];
#pragma unroll
        for (int nn = 0; nn < 4; nn++)
#pragma unroll
            for (int i = 0; i < 4; i++) s[nn][i] = 0.0f;

#pragma unroll
        for (int kk = 0; kk < HD; kk += 8) {
            int r = wr * 16 + lr;
            unsigned a0 = __float_as_uint(Qs[r * LDP + kk + lc]);
            unsigned a1 = __float_as_uint(Qs[(r + 8) * LDP + kk + lc]);
            unsigned a2 = __float_as_uint(Qs[r * LDP + kk + 4 + lc]);
            unsigned a3 = __float_as_uint(Qs[(r + 8) * LDP + kk + 4 + lc]);
#pragma unroll
            for (int nn = 0; nn < 4; nn++) {
                int n0 = wc * 32 + nn * 8;
                unsigned b0 = __float_as_uint(Ks[(n0 + lr) * LDP + kk + lc]);
                unsigned b1 = __float_as_uint(Ks[(n0 + lr) * LDP + kk + 4 + lc]);
                mma_tf32(s[nn], a0, a1, a2, a3, b0, b1);
            }
        }

        // scale + causal mask + store S to smem
        const bool diag = (kt == qt);
#pragma unroll
        for (int nn = 0; nn < 4; nn++) {
            int r = wr * 16 + lr;
            int c = wc * 32 + nn * 8 + 2 * lc;
            float v0 = s[nn][0] * SCALE, v1 = s[nn][1] * SCALE;
            float v2 = s[nn][2] * SCALE, v3 = s[nn][3] * SCALE;
            if (diag) {
                if (c     > r)     v0 = -1e30f;
                if (c + 1 > r)     v1 = -1e30f;
                if (c     > r + 8) v2 = -1e30f;
                if (c + 1 > r + 8) v3 = -1e30f;
            }
            Ss[r * LDP + c]           = v0;
            Ss[r * LDP + c + 1]       = v1;
            Ss[(r + 8) * LDP + c]     = v2;
            Ss[(r + 8) * LDP + c + 1] = v3;
        }
        __syncthreads();

        // online softmax: 4 lanes per row
        {
            const int r    = t >> 2;
            const int part = t & 3;
            const int cb   = part * 16;
            float mx = -1e30f;
#pragma unroll
            for (int c = 0; c < 16; c++) mx = fmaxf(mx, Ss[r * LDP + cb + c]);
            mx = fmaxf(mx, __shfl_xor_sync(0xffffffffu, mx, 1));
            mx = fmaxf(mx, __shfl_xor_sync(0xffffffffu, mx, 2));
            const float m_old = smM[r];
            const float m_new = fmaxf(m_old, mx);
            float sum = 0.0f;
#pragma unroll
            for (int c = 0; c < 16; c++) {
                float p = __expf(Ss[r * LDP + cb + c] - m_new);
                Ss[r * LDP + cb + c] = f2tf_f(p);   // tf32-round for PV MMA
                sum += p;
            }
            sum += __shfl_xor_sync(0xffffffffu, sum, 1);
            sum += __shfl_xor_sync(0xffffffffu, sum, 2);
            if (part == 0) {
                const float rf = __expf(m_old - m_new);
                smR[r] = rf;
                smM[r] = m_new;
                smL[r] = smL[r] * rf + sum;
            }
        }
        __syncthreads();

        // rescale O, then O += P * V (tf32 MMA)
        {
            const float f0 = smR[wr * 16 + lr];
            const float f1 = smR[wr * 16 + lr + 8];
#pragma unroll
            for (int nn = 0; nn < 4; nn++) {
                o[nn][0] *= f0; o[nn][1] *= f0;
                o[nn][2] *= f1; o[nn][3] *= f1;
            }
        }
#pragma unroll
        for (int kk = 0; kk < TILE; kk += 8) {
            int r = wr * 16 + lr;
            unsigned a0 = __float_as_uint(Ss[r * LDP + kk + lc]);
            unsigned a1 = __float_as_uint(Ss[(r + 8) * LDP + kk + lc]);
            unsigned a2 = __float_as_uint(Ss[r * LDP + kk + 4 + lc]);
            unsigned a3 = __float_as_uint(Ss[(r + 8) * LDP + kk + 4 + lc]);
#pragma unroll
            for (int nn = 0; nn < 4; nn++) {
                int n0 = wc * 32 + nn * 8;
                unsigned b0 = __float_as_uint(Vs[(kk + lc) * LDV + n0 + lr]);
                unsigned b1 = __float_as_uint(Vs[(kk + 4 + lc) * LDV + n0 + lr]);
                mma_tf32(o[nn], a0, a1, a2, a3, b0, b1);
            }
        }
        __syncthreads();   // protect Ks/Vs/Ss before next iteration
    }

    // final normalize + write
    {
        const float inv0 = 1.0f / smL[wr * 16 + lr];
        const float inv1 = 1.0f / smL[wr * 16 + lr + 8];
#pragma unroll
        for (int nn = 0; nn < 4; nn++) {
            int r = wr * 16 + lr;
            int c = wc * 32 + nn * 8 + 2 * lc;
            float2 v0 = make_float2(o[nn][0] * inv0, o[nn][1] * inv0);
            float2 v1 = make_float2(o[nn][2] * inv1, o[nn][3] * inv1);
            *(float2*)&out[(baseRow + q0 + r) * HD + c]     = v0;
            *(float2*)&out[(baseRow + q0 + r + 8) * HD + c] = v1;
        }
    }
}

// ---------------------------------------------------------------------------
extern "C" void kernel_launch(void* const* d_in, const int* in_sizes, int n_in,
                              void* d_out, int out_size)
{
    const float* emb = (const float*)d_in[0];
    const float* Wq  = (const float*)d_in[1];
    const float* Wk  = (const float*)d_in[2];
    const float* Wv  = (const float*)d_in[3];
    float* out = (float*)d_out;

    dim3 gq(MROWS / 128, 3);
    qkv_kernel<<<gq, 256>>>(emb, Wq, Wk, Wv);

    const int smem_bytes = SMEM_FLOATS * (int)sizeof(float);
    cudaFuncSetAttribute(attn_kernel, cudaFuncAttributeMaxDynamicSharedMemorySize, smem_bytes);
    dim3 ga(TT / TILE, BB);
    attn_kernel<<<ga, 256, smem_bytes>>>(out);
}

// round 11
// speedup vs baseline: 5.5109x; 1.9980x over previous
#include <cuda_runtime.h>
#include <cuda_fp16.h>

#define BB   4
#define TT   4096
#define EE   1024
#define HD   64
#define MROWS (BB * TT)
#define SCALE 0.03125f

// Projected q,k,v in fp16, [token][64]
__device__ __half g_q[MROWS * HD];
__device__ __half g_k[MROWS * HD];
__device__ __half g_v[MROWS * HD];

// ---------------- PTX helpers ----------------
__device__ __forceinline__ unsigned f2tf(float x) {
    unsigned r; asm("cvt.rna.tf32.f32 %0, %1;" : "=r"(r) : "f"(x)); return r;
}
__device__ __forceinline__ float f2tf_f(float x) { return __uint_as_float(f2tf(x)); }

__device__ __forceinline__ void mma_tf32(float c[4],
    unsigned a0, unsigned a1, unsigned a2, unsigned a3, unsigned b0, unsigned b1)
{
    asm volatile(
        "mma.sync.aligned.m16n8k8.row.col.f32.tf32.tf32.f32 "
        "{%0,%1,%2,%3}, {%4,%5,%6,%7}, {%8,%9}, {%0,%1,%2,%3};"
        : "+f"(c[0]), "+f"(c[1]), "+f"(c[2]), "+f"(c[3])
        : "r"(a0), "r"(a1), "r"(a2), "r"(a3), "r"(b0), "r"(b1));
}

__device__ __forceinline__ void mma_f16(float c[4],
    unsigned a0, unsigned a1, unsigned a2, unsigned a3, unsigned b0, unsigned b1)
{
    asm volatile(
        "mma.sync.aligned.m16n8k16.row.col.f32.f16.f16.f32 "
        "{%0,%1,%2,%3}, {%4,%5,%6,%7}, {%8,%9}, {%0,%1,%2,%3};"
        : "+f"(c[0]), "+f"(c[1]), "+f"(c[2]), "+f"(c[3])
        : "r"(a0), "r"(a1), "r"(a2), "r"(a3), "r"(b0), "r"(b1));
}

__device__ __forceinline__ void ldm_x4(unsigned &r0, unsigned &r1, unsigned &r2, unsigned &r3, unsigned addr) {
    asm volatile("ldmatrix.sync.aligned.m8n8.x4.shared.b16 {%0,%1,%2,%3}, [%4];"
        : "=r"(r0), "=r"(r1), "=r"(r2), "=r"(r3) : "r"(addr));
}
__device__ __forceinline__ void ldm_x4t(unsigned &r0, unsigned &r1, unsigned &r2, unsigned &r3, unsigned addr) {
    asm volatile("ldmatrix.sync.aligned.m8n8.x4.trans.shared.b16 {%0,%1,%2,%3}, [%4];"
        : "=r"(r0), "=r"(r1), "=r"(r2), "=r"(r3) : "r"(addr));
}

__device__ __forceinline__ void cpa16(void* smem_dst, const void* gsrc) {
    unsigned s = (unsigned)__cvta_generic_to_shared(smem_dst);
    asm volatile("cp.async.cg.shared.global [%0], [%1], 16;" :: "r"(s), "l"(gsrc));
}
__device__ __forceinline__ void cpa_commit() { asm volatile("cp.async.commit_group;"); }
__device__ __forceinline__ void cpa_wait0()  { asm volatile("cp.async.wait_group 0;" ::: "memory"); }

// ---------------------------------------------------------------------------
// Kernel 1: QKV projection via tf32 MMA, output fp16.
// ---------------------------------------------------------------------------
__global__ __launch_bounds__(256) void qkv_kernel(
    const float* __restrict__ emb,
    const float* __restrict__ Wq,
    const float* __restrict__ Wk,
    const float* __restrict__ Wv)
{
    const float* W   = (blockIdx.y == 0) ? Wq : (blockIdx.y == 1) ? Wk : Wv;
    __half*      out = (blockIdx.y == 0) ? g_q : (blockIdx.y == 1) ? g_k : g_v;

    __shared__ float As[128][20];
    __shared__ float Ws[64][20];

    const int t    = threadIdx.x;
    const int warp = t >> 5;
    const int lane = t & 31;
    const int lr   = lane >> 2;
    const int lc   = lane & 3;
    const int wr   = warp >> 1;
    const int wc   = warp & 1;
    const int m0   = blockIdx.x * 128;

    float acc[2][4][4];
#pragma unroll
    for (int mm = 0; mm < 2; mm++)
#pragma unroll
        for (int nn = 0; nn < 4; nn++)
#pragma unroll
            for (int i = 0; i < 4; i++) acc[mm][nn][i] = 0.0f;

    for (int k0 = 0; k0 < EE; k0 += 16) {
#pragma unroll
        for (int i = t; i < 512; i += 256) {
            int row = i >> 2, c4 = (i & 3) * 4;
            float4 v = *(const float4*)&emb[(size_t)(m0 + row) * EE + k0 + c4];
            As[row][c4 + 0] = f2tf_f(v.x); As[row][c4 + 1] = f2tf_f(v.y);
            As[row][c4 + 2] = f2tf_f(v.z); As[row][c4 + 3] = f2tf_f(v.w);
        }
        {
            int row = t >> 2, c4 = (t & 3) * 4;
            float4 v = *(const float4*)&W[(size_t)row * EE + k0 + c4];
            Ws[row][c4 + 0] = f2tf_f(v.x); Ws[row][c4 + 1] = f2tf_f(v.y);
            Ws[row][c4 + 2] = f2tf_f(v.z); Ws[row][c4 + 3] = f2tf_f(v.w);
        }
        __syncthreads();

#pragma unroll
        for (int kk = 0; kk < 16; kk += 8) {
            unsigned a[2][4];
#pragma unroll
            for (int mm = 0; mm < 2; mm++) {
                int r = wr * 32 + mm * 16 + lr;
                a[mm][0] = __float_as_uint(As[r    ][kk + lc]);
                a[mm][1] = __float_as_uint(As[r + 8][kk + lc]);
                a[mm][2] = __float_as_uint(As[r    ][kk + 4 + lc]);
                a[mm][3] = __float_as_uint(As[r + 8][kk + 4 + lc]);
            }
#pragma unroll
            for (int nn = 0; nn < 4; nn++) {
                int n0 = wc * 32 + nn * 8;
                unsigned b0 = __float_as_uint(Ws[n0 + lr][kk + lc]);
                unsigned b1 = __float_as_uint(Ws[n0 + lr][kk + 4 + lc]);
                mma_tf32(acc[0][nn], a[0][0], a[0][1], a[0][2], a[0][3], b0, b1);
                mma_tf32(acc[1][nn], a[1][0], a[1][1], a[1][2], a[1][3], b0, b1);
            }
        }
        __syncthreads();
    }

#pragma unroll
    for (int mm = 0; mm < 2; mm++)
#pragma unroll
        for (int nn = 0; nn < 4; nn++) {
            int r = m0 + wr * 32 + mm * 16 + lr;
            int c = wc * 32 + nn * 8 + 2 * lc;
            __half2 h0 = __floats2half2_rn(acc[mm][nn][0], acc[mm][nn][1]);
            __half2 h1 = __floats2half2_rn(acc[mm][nn][2], acc[mm][nn][3]);
            *(__half2*)&out[(size_t)r * HD + c]       = h0;
            *(__half2*)&out[(size_t)(r + 8) * HD + c] = h1;
        }
}

// ---------------------------------------------------------------------------
// Kernel 2: flash attention, fp16 MMA, register softmax, cp.async double buffer.
// Grid: 256 CTAs (load-balanced bid->job map). Block: 128 threads (4 warps).
// Warp = 16 q-rows x 64 keys. Q-tile 64, K-tile 64.
// ---------------------------------------------------------------------------
#define LDH 72   // halves per smem tile row (144B: conflict-free ldmatrix phases)

__global__ __launch_bounds__(128, 2) void attn_kernel(float* __restrict__ out)
{
    __shared__ __align__(16) __half Ks[2][64 * LDH];
    __shared__ __align__(16) __half Vs[2][64 * LDH];
    __shared__ __align__(16) __half Qsm[64 * LDH];

    const int t    = threadIdx.x;
    const int warp = t >> 5;
    const int lane = t & 31;
    const int lr   = lane >> 2;
    const int lc   = lane & 3;
    const int mb   = warp * 16;              // warp's q-row base within tile

    // balanced bid -> (batch, qt): bid<148 longest-first, bid>=148 complementary shortest
    const int bid  = blockIdx.x;
    const int rank = (bid < 148) ? bid : (403 - bid);
    const int qt   = 63 - (rank >> 2);
    const int b    = rank & 3;
    const int q0   = qt * 64;
    const size_t base = (size_t)b * TT;

    // ldmatrix lane address offsets (shared by Q/K/V patterns)
    const int ro = (lane & 7) + ((lane >> 3) & 1) * 8;   // row-within-16
    const int co = (lane >> 4) * 8;                      // col-within-16

    // ---- prologue: stage Q + K/V tile 0 ----
    for (int i = t; i < 512; i += 128) {
        int row = i >> 3, c8 = (i & 7) * 8;
        cpa16(&Qsm[row * LDH + c8],   &g_q[(base + q0 + row) * HD + c8]);
        cpa16(&Ks[0][row * LDH + c8], &g_k[(base + row) * HD + c8]);
        cpa16(&Vs[0][row * LDH + c8], &g_v[(base + row) * HD + c8]);
    }
    cpa_commit();
    cpa_wait0();
    __syncthreads();

    // Q fragments (persistent in registers)
    unsigned qa[4][4];
#pragma unroll
    for (int s = 0; s < 4; s++) {
        unsigned addr = (unsigned)__cvta_generic_to_shared(
            &Qsm[(mb + ro) * LDH + s * 16 + co]);
        ldm_x4(qa[s][0], qa[s][1], qa[s][2], qa[s][3], addr);
    }

    float o[8][4];
#pragma unroll
    for (int j = 0; j < 8; j++)
#pragma unroll
        for (int i = 0; i < 4; i++) o[j][i] = 0.0f;
    float m0r = -1e30f, m1r = -1e30f, l0 = 0.0f, l1 = 0.0f;

    const unsigned ks_u[2] = {
        (unsigned)__cvta_generic_to_shared(&Ks[0][(ro) * LDH + co]),
        (unsigned)__cvta_generic_to_shared(&Ks[1][(ro) * LDH + co]) };
    const unsigned vs_u[2] = {
        (unsigned)__cvta_generic_to_shared(&Vs[0][(ro) * LDH + co]),
        (unsigned)__cvta_generic_to_shared(&Vs[1][(ro) * LDH + co]) };

    for (int kt = 0; kt <= qt; kt++) {
        const int cur = kt & 1;

        // prefetch next K/V tile
        if (kt < qt) {
            const int k0n = (kt + 1) * 64;
            for (int i = t; i < 512; i += 128) {
                int row = i >> 3, c8 = (i & 7) * 8;
                cpa16(&Ks[cur ^ 1][row * LDH + c8], &g_k[(base + k0n + row) * HD + c8]);
                cpa16(&Vs[cur ^ 1][row * LDH + c8], &g_v[(base + k0n + row) * HD + c8]);
            }
            cpa_commit();
        }

        // ---- S = Q K^T ----
        float sa[8][4];
#pragma unroll
        for (int j = 0; j < 8; j++)
#pragma unroll
            for (int i = 0; i < 4; i++) sa[j][i] = 0.0f;

#pragma unroll
        for (int s = 0; s < 4; s++) {
#pragma unroll
            for (int jn2 = 0; jn2 < 4; jn2++) {
                unsigned r0, r1, r2, r3;
                ldm_x4(r0, r1, r2, r3, ks_u[cur] + (unsigned)((jn2 * 16 * LDH + s * 16) * 2));
                mma_f16(sa[jn2 * 2],     qa[s][0], qa[s][1], qa[s][2], qa[s][3], r0, r2);
                mma_f16(sa[jn2 * 2 + 1], qa[s][0], qa[s][1], qa[s][2], qa[s][3], r1, r3);
            }
        }

        // scale + causal mask (diagonal tile only)
#pragma unroll
        for (int j = 0; j < 8; j++)
#pragma unroll
            for (int i = 0; i < 4; i++) sa[j][i] *= SCALE;
        if (kt == qt) {
            const int r0l = mb + lr, r1l = mb + lr + 8;
#pragma unroll
            for (int j = 0; j < 8; j++) {
                int c = j * 8 + 2 * lc;
                if (c     > r0l) sa[j][0] = -1e30f;
                if (c + 1 > r0l) sa[j][1] = -1e30f;
                if (c     > r1l) sa[j][2] = -1e30f;
                if (c + 1 > r1l) sa[j][3] = -1e30f;
            }
        }

        // ---- register softmax (rows lr, lr+8; quad shfl reduce) ----
        float mx0 = -1e30f, mx1 = -1e30f;
#pragma unroll
        for (int j = 0; j < 8; j++) {
            mx0 = fmaxf(mx0, fmaxf(sa[j][0], sa[j][1]));
            mx1 = fmaxf(mx1, fmaxf(sa[j][2], sa[j][3]));
        }
        mx0 = fmaxf(mx0, __shfl_xor_sync(0xffffffffu, mx0, 1));
        mx0 = fmaxf(mx0, __shfl_xor_sync(0xffffffffu, mx0, 2));
        mx1 = fmaxf(mx1, __shfl_xor_sync(0xffffffffu, mx1, 1));
        mx1 = fmaxf(mx1, __shfl_xor_sync(0xffffffffu, mx1, 2));

        const float mn0 = fmaxf(m0r, mx0), mn1 = fmaxf(m1r, mx1);
        const float rf0 = __expf(m0r - mn0), rf1 = __expf(m1r - mn1);
        m0r = mn0; m1r = mn1;

        unsigned pf[4][4];
        float sum0 = 0.0f, sum1 = 0.0f;
#pragma unroll
        for (int j = 0; j < 8; j++) {
            float p0 = __expf(sa[j][0] - mn0);
            float p1 = __expf(sa[j][1] - mn0);
            float p2 = __expf(sa[j][2] - mn1);
            float p3 = __expf(sa[j][3] - mn1);
            sum0 += p0 + p1; sum1 += p2 + p3;
            __half2 h01 = __floats2half2_rn(p0, p1);
            __half2 h23 = __floats2half2_rn(p2, p3);
            int s = j >> 1;
            if ((j & 1) == 0) { pf[s][0] = *(unsigned*)&h01; pf[s][1] = *(unsigned*)&h23; }
            else              { pf[s][2] = *(unsigned*)&h01; pf[s][3] = *(unsigned*)&h23; }
        }
        sum0 += __shfl_xor_sync(0xffffffffu, sum0, 1);
        sum0 += __shfl_xor_sync(0xffffffffu, sum0, 2);
        sum1 += __shfl_xor_sync(0xffffffffu, sum1, 1);
        sum1 += __shfl_xor_sync(0xffffffffu, sum1, 2);
        l0 = l0 * rf0 + sum0;
        l1 = l1 * rf1 + sum1;

        // rescale O
#pragma unroll
        for (int j = 0; j < 8; j++) {
            o[j][0] *= rf0; o[j][1] *= rf0;
            o[j][2] *= rf1; o[j][3] *= rf1;
        }

        // ---- O += P V ----
#pragma unroll
        for (int s = 0; s < 4; s++) {
#pragma unroll
            for (int jh2 = 0; jh2 < 4; jh2++) {
                unsigned r0, r1, r2, r3;
                ldm_x4t(r0, r1, r2, r3, vs_u[cur] + (unsigned)((s * 16 * LDH + jh2 * 16) * 2));
                mma_f16(o[jh2 * 2],     pf[s][0], pf[s][1], pf[s][2], pf[s][3], r0, r1);
                mma_f16(o[jh2 * 2 + 1], pf[s][0], pf[s][1], pf[s][2], pf[s][3], r2, r3);
            }
        }

        if (kt < qt) {
            cpa_wait0();
            __syncthreads();
        }
    }

    // ---- epilogue ----
    const float inv0 = 1.0f / l0, inv1 = 1.0f / l1;
#pragma unroll
    for (int j = 0; j < 8; j++) {
        int c = j * 8 + 2 * lc;
        size_t r0g = (base + q0 + mb + lr) * HD + c;
        size_t r1g = (base + q0 + mb + lr + 8) * HD + c;
        *(float2*)&out[r0g] = make_float2(o[j][0] * inv0, o[j][1] * inv0);
        *(float2*)&out[r1g] = make_float2(o[j][2] * inv1, o[j][3] * inv1);
    }
}

// ---------------------------------------------------------------------------
extern "C" void kernel_launch(void* const* d_in, const int* in_sizes, int n_in,
                              void* d_out, int out_size)
{
    const float* emb = (const float*)d_in[0];
    const float* Wq  = (const float*)d_in[1];
    const float* Wk  = (const float*)d_in[2];
    const float* Wv  = (const float*)d_in[3];
    float* out = (float*)d_out;

    dim3 gq(MROWS / 128, 3);
    qkv_kernel<<<gq, 256>>>(emb, Wq, Wk, Wv);

    attn_kernel<<<256, 128>>>(out);
}